// round 1
// baseline (speedup 1.0000x reference)
#include <cuda_runtime.h>

#define Hh 96
#define Ww 96
#define TPB 288   // 24 h-groups (x4 rows) * 12 w-groups (x8 cols)

__device__ __forceinline__ unsigned long long ffma2(unsigned long long a,
                                                    unsigned long long b,
                                                    unsigned long long c) {
    unsigned long long d;
    asm("fma.rn.f32x2 %0, %1, %2, %3;" : "=l"(d) : "l"(a), "l"(b), "l"(c));
    return d;
}

__global__ __launch_bounds__(TPB) void conv_h_kernel(
    const float* __restrict__ x, const float* __restrict__ pe,
    const float* __restrict__ wt, const float* __restrict__ bias,
    const float* __restrict__ rw, float* __restrict__ out, int C)
{
    __shared__ __align__(16) float xs[Hh][Ww];   // 36 KB input tile (pe added)
    __shared__ __align__(16) float2 wrv[192];    // reversed-doubled, pre-splatted weights

    const int bc = blockIdx.x;        // b*C + c
    const int c  = bc % C;
    const int t  = threadIdx.x;

    const float* xp  = x + (size_t)bc * (Hh * Ww);
    const float* pep = pe + c * Hh;

    // Load tile, fusing the positional-embedding add. 2304 float4s / 288 thr = 8 iters.
    #pragma unroll
    for (int i = t; i < (Hh * Ww) / 4; i += TPB) {
        float4 v = ((const float4*)xp)[i];
        float p = pep[i / 24];   // row h = (4*i)/96 = i/24 (all 4 elems same row)
        v.x += p; v.y += p; v.z += p; v.w += p;
        ((float4*)&xs[0][0])[i] = v;
    }

    // Combined weight wc[k] = wt[c,k] + (k<3 ? rw[c,k] : 0), stored reversed-doubled:
    // wrv[t] = wc[(191 - t) % 96], splatted to float2 so the inner loop is LDS.64.
    if (t < 192) {
        int idx = (191 - t) % Hh;
        float wv = wt[c * Hh + idx];
        if (idx < 3) wv += rw[c * 3 + idx];
        wrv[t] = make_float2(wv, wv);
    }
    __syncthreads();

    const int ty = t / 12, tx = t % 12;
    const int h0 = ty * 4, w0 = tx * 8;

    const float bv = bias[c];
    unsigned long long binit;
    asm("mov.b64 %0, {%1, %1};" : "=l"(binit) : "f"(bv));

    unsigned long long acc[4][4];
    #pragma unroll
    for (int r = 0; r < 4; r++)
        #pragma unroll
        for (int p = 0; p < 4; p++) acc[r][p] = binit;

    const unsigned long long* wv2 = (const unsigned long long*)wrv;

    // out[h][w] = bias + sum_j wc[(j-h) mod 96] * xs[j][w]
    // weight access: wrv[95 - j + h] == wc[(j-h+96) % 96]
    #pragma unroll 4
    for (int j = 0; j < Hh; j++) {
        const unsigned long long* xr = (const unsigned long long*)&xs[j][w0];
        unsigned long long x0 = xr[0], x1 = xr[1], x2 = xr[2], x3 = xr[3];
        int base = 95 - j + h0;
        #pragma unroll
        for (int r = 0; r < 4; r++) {
            unsigned long long m = wv2[base + r];
            acc[r][0] = ffma2(m, x0, acc[r][0]);
            acc[r][1] = ffma2(m, x1, acc[r][1]);
            acc[r][2] = ffma2(m, x2, acc[r][2]);
            acc[r][3] = ffma2(m, x3, acc[r][3]);
        }
    }

    float* op = out + (size_t)bc * (Hh * Ww);
    #pragma unroll
    for (int r = 0; r < 4; r++) {
        union { unsigned long long u; float2 f; } a0, a1, a2, a3;
        a0.u = acc[r][0]; a1.u = acc[r][1]; a2.u = acc[r][2]; a3.u = acc[r][3];
        float4 v0 = make_float4(a0.f.x, a0.f.y, a1.f.x, a1.f.y);
        float4 v1 = make_float4(a2.f.x, a2.f.y, a3.f.x, a3.f.y);
        float4* orow = (float4*)&op[(h0 + r) * Ww + w0];
        orow[0] = v0;
        orow[1] = v1;
    }
}

extern "C" void kernel_launch(void* const* d_in, const int* in_sizes, int n_in,
                              void* d_out, int out_size) {
    const float* x    = (const float*)d_in[0];
    const float* pe   = (const float*)d_in[1];
    const float* wt   = (const float*)d_in[2];
    const float* bias = (const float*)d_in[3];
    const float* rw   = (const float*)d_in[4];
    float* out = (float*)d_out;

    const int nblocks = in_sizes[0] / (Hh * Ww);  // B*C = 4096
    const int C       = in_sizes[2] / Hh;         // 256

    conv_h_kernel<<<nblocks, TPB>>>(x, pe, wt, bias, rw, out, C);
}

// round 2
// speedup vs baseline: 2.3332x; 2.3332x over previous
#include <cuda_runtime.h>

#define Hh 96
#define Ww 96
#define TPB 576   // 12 h-groups (x8 rows) * 48 w-groups (x2 cols, f32x2)

typedef unsigned long long u64;

__device__ __forceinline__ u64 ffma2(u64 a, u64 b, u64 c) {
    u64 d;
    asm("fma.rn.f32x2 %0, %1, %2, %3;" : "=l"(d) : "l"(a), "l"(b), "l"(c));
    return d;
}

__global__ __launch_bounds__(TPB, 2) void conv_h_kernel(
    const float* __restrict__ x, const float* __restrict__ pe,
    const float* __restrict__ wt, const float* __restrict__ bias,
    const float* __restrict__ rw, float* __restrict__ out, int C)
{
    __shared__ __align__(16) float xs[Hh][Ww];     // 36 KB input tile (pe added)
    __shared__ __align__(16) float2 wrvA[194];     // logical idx i in [-1,192] at wrvA[i+1], splatted

    const int bc = blockIdx.x;        // b*C + c
    const int c  = bc % C;
    const int t  = threadIdx.x;

    const float* xp  = x + (size_t)bc * (Hh * Ww);
    const float* pep = pe + c * Hh;

    // Load tile, fusing positional-embedding add. 2304 float4s / 576 thr = 4 iters.
    #pragma unroll
    for (int i = t; i < (Hh * Ww) / 4; i += TPB) {
        float4 v = ((const float4*)xp)[i];
        float p = pep[i / 24];   // all 4 elems of a float4 are in row i/24
        v.x += p; v.y += p; v.z += p; v.w += p;
        ((float4*)&xs[0][0])[i] = v;
    }

    // Combined weight wc[k] = wt[c,k] + (k<3 ? rw[c,k] : 0).
    // A(i) := wc[(191 - i) mod 96], stored splatted at wrvA[i+1], i = -1..192.
    if (t < 194) {
        int idx = (192 - t) % Hh;          // (191 - (t-1)) mod 96
        float wv = wt[c * Hh + idx];
        if (idx < 3) wv += rw[c * 3 + idx];
        wrvA[t] = make_float2(wv, wv);
    }
    __syncthreads();

    const int ty = t / 48, wx = t % 48;    // h0 = ty*8, w-pair = wx
    const int h0 = ty * 8;

    const u64* wA = (const u64*)wrvA + 1;  // logical index

    const float bv = bias[c];
    u64 binit;
    asm("mov.b64 %0, {%1, %1};" : "=l"(binit) : "f"(bv));

    u64 acc[8];
    #pragma unroll
    for (int r = 0; r < 8; r++) acc[r] = binit;

    // Weight ring: at iteration jj, weight(r) = A(95-jj+h0+r) = ring[(r-jj)&7].
    u64 ring[8];
    #pragma unroll
    for (int i = 0; i < 8; i++) ring[i] = wA[95 + h0 + i];

    const u64* xcol = (const u64*)&xs[0][0] + wx;   // f32x2 column, row stride 48

    u64 xv = xcol[0];
    // out[h0+r][2wx..2wx+1] = bias + sum_jj A(95-jj+h0+r) * xs[jj][2wx..]
    #pragma unroll
    for (int jj = 0; jj < Hh; jj++) {
        u64 xn = (jj < Hh - 1) ? xcol[(jj + 1) * 48] : 0ULL;
        u64 wn = wA[94 - jj + h0];          // weight(0) for jj+1 (prefetch)
        #pragma unroll
        for (int r = 0; r < 8; r++)
            acc[r] = ffma2(ring[(r - jj) & 7], xv, acc[r]);
        ring[(7 - jj) & 7] = wn;            // compile-time slot -> register rename
        xv = xn;
    }

    float* op = out + (size_t)bc * (Hh * Ww) + wx * 2;
    #pragma unroll
    for (int r = 0; r < 8; r++) {
        union { u64 u; float2 f; } a; a.u = acc[r];
        *(float2*)&op[(h0 + r) * Ww] = a.f;
    }
}

extern "C" void kernel_launch(void* const* d_in, const int* in_sizes, int n_in,
                              void* d_out, int out_size) {
    const float* x    = (const float*)d_in[0];
    const float* pe   = (const float*)d_in[1];
    const float* wt   = (const float*)d_in[2];
    const float* bias = (const float*)d_in[3];
    const float* rw   = (const float*)d_in[4];
    float* out = (float*)d_out;

    const int nblocks = in_sizes[0] / (Hh * Ww);  // B*C = 4096
    const int C       = in_sizes[2] / Hh;         // 256

    conv_h_kernel<<<nblocks, TPB>>>(x, pe, wt, bias, rw, out, C);
}